// round 4
// baseline (speedup 1.0000x reference)
#include <cuda_runtime.h>

#define NB 8
#define T 16
#define C 256
#define CM 64
#define AA 32
#define HW 784
#define HWC (HW*C)        /* 200704 */
#define X4F (HWC/4)       /* 50176 float4 per frame */
#define CB 4              /* videos per chunk */
#define NBLK 296          /* 2 CTAs per SM, guaranteed co-resident */
#define SLOTS 32          /* partial slots per frame: 8 segs x 4 pi-rows */

// Scratch (allocation-free rule: __device__ globals)
__device__ float g_partial[NB*T*SLOTS*C];   // 4 MB
__device__ float g_kern[NB*3*C];            // [b][k][c]
__device__ float g_act[NB*T*C];             // [b][t][c]
__device__ unsigned g_bar_cnt;              // zero-init; self-resetting
__device__ volatile unsigned g_bar_rel;     // monotonically increasing epoch

// ---- grid-wide barrier (all NBLK blocks resident => no deadlock) ----
__device__ __forceinline__ void grid_bar() {
    __syncthreads();
    __threadfence();
    if (threadIdx.x == 0) {
        unsigned epoch = g_bar_rel;              // read BEFORE arriving
        if (atomicAdd(&g_bar_cnt, 1u) == NBLK - 1u) {
            g_bar_cnt = 0;
            __threadfence();
            g_bar_rel = epoch + 1u;
        } else {
            while (g_bar_rel == epoch) __nanosleep(64);
        }
    }
    __syncthreads();
    __threadfence();
}

// ---- phase P: spatial partial sums for frames [n0, n0+nf) ----
__device__ __forceinline__ void phaseP(const float4* __restrict__ x4,
                                       int n0, int nf, int jb, int stride,
                                       int c4, int pi) {
    int njobs = nf * 8;
    for (int job = jb; job < njobs; job += stride) {
        int n  = n0 + (job >> 3);
        int s8 = job & 7;
        const float4* xp = x4 + (size_t)n*X4F + (size_t)(s8*98 + pi)*64 + c4;
        int cnt = (pi < 2) ? 25 : 24;
        float4 a0 = make_float4(0,0,0,0), a1 = a0, a2 = a0, a3 = a0;
        int i = 0;
        for (; i + 3 < cnt; i += 4) {
            float4 v0 = xp[(size_t)(i+0)*256];
            float4 v1 = xp[(size_t)(i+1)*256];
            float4 v2 = xp[(size_t)(i+2)*256];
            float4 v3 = xp[(size_t)(i+3)*256];
            a0.x+=v0.x; a0.y+=v0.y; a0.z+=v0.z; a0.w+=v0.w;
            a1.x+=v1.x; a1.y+=v1.y; a1.z+=v1.z; a1.w+=v1.w;
            a2.x+=v2.x; a2.y+=v2.y; a2.z+=v2.z; a2.w+=v2.w;
            a3.x+=v3.x; a3.y+=v3.y; a3.z+=v3.z; a3.w+=v3.w;
        }
        for (; i < cnt; i++) {
            float4 v = xp[(size_t)i*256];
            a0.x+=v.x; a0.y+=v.y; a0.z+=v.z; a0.w+=v.w;
        }
        float4 r;
        r.x = (a0.x+a1.x)+(a2.x+a3.x);
        r.y = (a0.y+a1.y)+(a2.y+a3.y);
        r.z = (a0.z+a1.z)+(a2.z+a3.z);
        r.w = (a0.w+a1.w)+(a2.w+a3.w);
        ((float4*)g_partial)[((size_t)n*SLOTS + s8*4 + pi)*64 + c4] = r;
    }
}

// ---- phase Br: branch math for videos [b0, b0+CB). 68 jobs. ----
__device__ __forceinline__ void phaseBr(float* sh, int b0, int j, int tid,
        const float* __restrict__ gw1, const float* __restrict__ ggam,
        const float* __restrict__ gbet, const float* __restrict__ gmean,
        const float* __restrict__ gvar, const float* __restrict__ gw2,
        const float* __restrict__ lw1, const float* __restrict__ lgam,
        const float* __restrict__ lbet, const float* __restrict__ lmean,
        const float* __restrict__ lvar, const float* __restrict__ lw2) {
    if (j < CB*T) {
        // local branch for (b, t): conv(3,256->64)->bn/relu->conv(1,64->256)->sigmoid
        int b = b0 + j/T, t = j%T;
        float* th_s = sh;          // 768
        float* red  = sh + 768;    // 256
        float* l_s  = sh + 1024;   // 64
        #pragma unroll
        for (int dt = 0; dt < 3; dt++) {
            int tt = t + dt - 1;
            float s = 0.f;
            if (tt >= 0 && tt < T) {
                #pragma unroll 8
                for (int ss = 0; ss < SLOTS; ss++)
                    s += g_partial[((size_t)(b*T + tt)*SLOTS + ss)*C + tid];
                s *= (1.0f/(float)HW);
            }
            th_s[dt*C + tid] = s;
        }
        __syncthreads();
        int m = tid & 63, part = tid >> 6;
        float acc = 0.f;
        #pragma unroll 8
        for (int i = 0; i < 192; i++) {
            int jj = part*192 + i;                // jj = dt*256 + c
            acc += th_s[jj] * lw1[jj*CM + m];
        }
        red[tid] = acc;
        __syncthreads();
        if (tid < CM) {
            float v = red[tid] + red[tid+64] + red[tid+128] + red[tid+192];
            float inv = rsqrtf(lvar[tid] + 1e-3f);
            v = (v - lmean[tid]) * (lgam[tid] * inv) + lbet[tid];
            l_s[tid] = fmaxf(v, 0.f);
        }
        __syncthreads();
        float o = 0.f;
        #pragma unroll 8
        for (int mm = 0; mm < CM; mm++) o += l_s[mm] * lw2[mm*C + tid];
        g_act[(b*T + t)*C + tid] = 1.f/(1.f + expf(-o));
    } else if (j < CB*T + CB) {
        // global branch for b: Dense(16->32)->bn/relu->Dense(32->3)->softmax
        int b = b0 + (j - CB*T), c = tid;
        float th[T];
        #pragma unroll
        for (int t = 0; t < T; t++) {
            float s = 0.f;
            #pragma unroll 8
            for (int ss = 0; ss < SLOTS; ss++)
                s += g_partial[((size_t)(b*T + t)*SLOTS + ss)*C + c];
            th[t] = s * (1.0f/(float)HW);
        }
        float lg0 = 0.f, lg1 = 0.f, lg2 = 0.f;
        #pragma unroll 4
        for (int a = 0; a < AA; a++) {
            float g = 0.f;
            #pragma unroll
            for (int t = 0; t < T; t++) g += th[t] * gw1[t*AA + a];
            float inv = rsqrtf(gvar[a] + 1e-3f);
            g = (g - gmean[a]) * (ggam[a] * inv) + gbet[a];
            g = fmaxf(g, 0.f);
            lg0 += g * gw2[a*3 + 0];
            lg1 += g * gw2[a*3 + 1];
            lg2 += g * gw2[a*3 + 2];
        }
        float mx = fmaxf(lg0, fmaxf(lg1, lg2));
        float e0 = expf(lg0 - mx), e1 = expf(lg1 - mx), e2 = expf(lg2 - mx);
        float inv = 1.f/(e0 + e1 + e2);
        g_kern[(b*3 + 0)*C + c] = e0*inv;
        g_kern[(b*3 + 1)*C + c] = e1*inv;
        g_kern[(b*3 + 2)*C + c] = e2*inv;
    }
}

// ---- phase A: gated adaptive temporal conv for video b, pb tiles [pb0,pb1) ----
__device__ __forceinline__ void phaseA(const float4* __restrict__ x4,
                                       float4* __restrict__ y4, float* sh,
                                       int b, int pb0, int pb1,
                                       int tid, int c4, int pi) {
    // build coef[t][k][c] = kern[b,c,k] * act[b,c,t-1+k] in 48KB smem
    float k0 = g_kern[(b*3 + 0)*C + tid];
    float k1 = g_kern[(b*3 + 1)*C + tid];
    float k2 = g_kern[(b*3 + 2)*C + tid];
    sh[(0*3 + 0)*C + tid]  = 0.f;
    sh[(15*3 + 2)*C + tid] = 0.f;
    #pragma unroll
    for (int ts = 0; ts < T; ts++) {
        float a = g_act[(b*T + ts)*C + tid];
        #pragma unroll
        for (int k = 0; k < 3; k++) {
            int t = ts + 1 - k;
            if (t >= 0 && t < T) {
                float kk = (k == 0) ? k0 : ((k == 1) ? k1 : k2);
                sh[(t*3 + k)*C + tid] = kk * a;
            }
        }
    }
    __syncthreads();
    const float4* cs4 = (const float4*)sh;
    const int S4 = X4F;
    for (int pb = pb0; pb < pb1; pb++) {
        int p = pb*4 + pi;
        size_t base4 = (size_t)(b*T)*X4F + (size_t)p*64 + c4;
        const float4* xp = x4 + base4;
        float4*       yp = y4 + base4;
        float4 xm = make_float4(0.f,0.f,0.f,0.f);
        float4 xc = xp[0];
        #pragma unroll
        for (int t = 0; t < T; t++) {
            float4 xn = (t < T-1) ? xp[(size_t)(t+1)*S4] : make_float4(0.f,0.f,0.f,0.f);
            float4 c0 = cs4[(t*3 + 0)*64 + c4];
            float4 c1 = cs4[(t*3 + 1)*64 + c4];
            float4 c2 = cs4[(t*3 + 2)*64 + c4];
            float4 o;
            o.x = c0.x*xm.x + c1.x*xc.x + c2.x*xn.x;
            o.y = c0.y*xm.y + c1.y*xc.y + c2.y*xn.y;
            o.z = c0.z*xm.z + c1.z*xc.z + c2.z*xn.z;
            o.w = c0.w*xm.w + c1.w*xc.w + c2.w*xn.w;
            __stcs(yp + (size_t)t*S4, o);
            xm = xc; xc = xn;
        }
    }
    __syncthreads();
}

__global__ void __launch_bounds__(256, 2)
tam_persistent(const float4* __restrict__ x4, float4* __restrict__ y4,
        const float* __restrict__ gw1, const float* __restrict__ ggam,
        const float* __restrict__ gbet, const float* __restrict__ gmean,
        const float* __restrict__ gvar, const float* __restrict__ gw2,
        const float* __restrict__ lw1, const float* __restrict__ lgam,
        const float* __restrict__ lbet, const float* __restrict__ lmean,
        const float* __restrict__ lvar, const float* __restrict__ lw2) {
    __shared__ float sh[T*3*C];   // 48 KB, aliased across phases
    int bid = blockIdx.x, tid = threadIdx.x;
    int c4 = tid & 63, pi = tid >> 6;

    // P0: partial sums for chunk0 (frames 0..63), all 296 blocks
    phaseP(x4, 0, CB*T, bid, NBLK, c4, pi);
    grid_bar();
    // Br0: branch for chunk0 (68 jobs)
    phaseBr(sh, 0, bid, tid, gw1, ggam, gbet, gmean, gvar, gw2,
                            lw1, lgam, lbet, lmean, lvar, lw2);
    grid_bar();
    // M: A0 on chunk0 (blocks 0..199, x chunk0 L2-hot) || P1 on chunk1 (blocks 200..295)
    if (bid < 200) {
        int b  = bid / 50;
        int jj = bid % 50;
        phaseA(x4, y4, sh, b, jj*196/50, (jj+1)*196/50, tid, c4, pi);
    } else {
        phaseP(x4, CB*T, CB*T, bid - 200, NBLK - 200, c4, pi);
    }
    grid_bar();
    // Br1: branch for chunk1
    phaseBr(sh, CB, bid, tid, gw1, ggam, gbet, gmean, gvar, gw2,
                              lw1, lgam, lbet, lmean, lvar, lw2);
    grid_bar();
    // A1: agg chunk1 (x chunk1 L2-hot from P1), all 296 blocks
    {
        int b  = CB + bid / 74;
        int jj = bid % 74;
        phaseA(x4, y4, sh, b, jj*196/74, (jj+1)*196/74, tid, c4, pi);
    }
}

extern "C" void kernel_launch(void* const* d_in, const int* in_sizes, int n_in,
                              void* d_out, int out_size) {
    const float* x       = (const float*)d_in[0];
    const float* gw1     = (const float*)d_in[1];
    const float* ggamma  = (const float*)d_in[2];
    const float* gbeta   = (const float*)d_in[3];
    const float* gmean   = (const float*)d_in[4];
    const float* gvar    = (const float*)d_in[5];
    const float* gw2     = (const float*)d_in[6];
    const float* lw1     = (const float*)d_in[7];
    const float* lgamma  = (const float*)d_in[8];
    const float* lbeta   = (const float*)d_in[9];
    const float* lmean   = (const float*)d_in[10];
    const float* lvar    = (const float*)d_in[11];
    const float* lw2     = (const float*)d_in[12];
    float* y = (float*)d_out;

    tam_persistent<<<NBLK, 256>>>((const float4*)x, (float4*)y,
                                  gw1, ggamma, gbeta, gmean, gvar, gw2,
                                  lw1, lgamma, lbeta, lmean, lvar, lw2);
}

// round 5
// speedup vs baseline: 1.3209x; 1.3209x over previous
#include <cuda_runtime.h>

#define NB 8
#define T 16
#define C 256
#define CM 64
#define AA 32
#define HW 784
#define HWC (HW*C)        /* 200704 */
#define X4F (HWC/4)       /* 50176 float4 per frame */
#define NSPLIT 16
#define ROWS_PER_SEG 49   /* 784/16 */
#define SLOTS (NSPLIT*4)  /* 64 partial slots per frame */

// Scratch (allocation-free rule: __device__ globals)
__device__ float g_partial[NB*T*SLOTS*C];   // 8 MB
__device__ float g_kern[NB*3*C];            // [b][k][c]
__device__ float g_act[NB*T*C];             // [b][t][c]

// ---------------- K1: spatial partial sums, float4, high-occupancy ----------
__global__ void k_partial(const float4* __restrict__ x4) {
    int n = blockIdx.x, s = blockIdx.y, tid = threadIdx.x;
    int c4 = tid & 63, pi = tid >> 6;
    // rows covered by this thread: s*49 + pi, step 4; pi==0 gets 13 rows, else 12
    const float4* xp = x4 + (size_t)n*X4F + (size_t)(s*ROWS_PER_SEG + pi)*64 + c4;
    float4 a0 = make_float4(0,0,0,0), a1 = a0, a2 = a0, a3 = a0;
    #pragma unroll
    for (int i = 0; i < 12; i += 4) {
        float4 v0 = xp[(size_t)(i+0)*256];
        float4 v1 = xp[(size_t)(i+1)*256];
        float4 v2 = xp[(size_t)(i+2)*256];
        float4 v3 = xp[(size_t)(i+3)*256];
        a0.x+=v0.x; a0.y+=v0.y; a0.z+=v0.z; a0.w+=v0.w;
        a1.x+=v1.x; a1.y+=v1.y; a1.z+=v1.z; a1.w+=v1.w;
        a2.x+=v2.x; a2.y+=v2.y; a2.z+=v2.z; a2.w+=v2.w;
        a3.x+=v3.x; a3.y+=v3.y; a3.z+=v3.z; a3.w+=v3.w;
    }
    if (pi == 0) {   // 49th row of the segment
        float4 v = xp[(size_t)12*256];
        a0.x+=v.x; a0.y+=v.y; a0.z+=v.z; a0.w+=v.w;
    }
    float4 r;
    r.x = (a0.x+a1.x)+(a2.x+a3.x);
    r.y = (a0.y+a1.y)+(a2.y+a3.y);
    r.z = (a0.z+a1.z)+(a2.z+a3.z);
    r.w = (a0.w+a1.w)+(a2.w+a3.w);
    ((float4*)g_partial)[((size_t)n*SLOTS + s*4 + pi)*64 + c4] = r;
}

// ---------------- K2: fused branch kernel ----------------
// blocks [0, NB*T): local branch (per b,t) -> g_act
// blocks [NB*T, NB*T+NB): global branch (per b)  -> g_kern
__global__ void k_branch(const float* __restrict__ gw1, const float* __restrict__ ggam,
                         const float* __restrict__ gbet, const float* __restrict__ gmean,
                         const float* __restrict__ gvar, const float* __restrict__ gw2,
                         const float* __restrict__ lw1, const float* __restrict__ lgam,
                         const float* __restrict__ lbet, const float* __restrict__ lmean,
                         const float* __restrict__ lvar, const float* __restrict__ lw2) {
    int bid = blockIdx.x, tid = threadIdx.x;
    if (bid < NB*T) {
        int b = bid / T, t = bid % T;
        __shared__ float th_s[3*C];
        __shared__ float red[256];
        __shared__ float l_s[CM];
        #pragma unroll
        for (int dt = 0; dt < 3; dt++) {
            int tt = t + dt - 1;
            float s = 0.f;
            if (tt >= 0 && tt < T) {
                #pragma unroll 16
                for (int ss = 0; ss < SLOTS; ss++)
                    s += g_partial[((size_t)(b*T + tt)*SLOTS + ss)*C + tid];
                s *= (1.0f/(float)HW);
            }
            th_s[dt*C + tid] = s;
        }
        __syncthreads();
        int m = tid & 63, part = tid >> 6;
        float acc = 0.f;
        #pragma unroll 8
        for (int i = 0; i < 192; i++) {
            int j = part*192 + i;                 // j = dt*256 + c
            acc += th_s[j] * lw1[j*CM + m];
        }
        red[tid] = acc;
        __syncthreads();
        if (tid < CM) {
            float v = red[tid] + red[tid+64] + red[tid+128] + red[tid+192];
            float inv = rsqrtf(lvar[tid] + 1e-3f);
            v = (v - lmean[tid]) * (lgam[tid] * inv) + lbet[tid];
            l_s[tid] = fmaxf(v, 0.f);
        }
        __syncthreads();
        float o = 0.f;
        #pragma unroll 8
        for (int mm = 0; mm < CM; mm++) o += l_s[mm] * lw2[mm*C + tid];
        g_act[(b*T + t)*C + tid] = 1.f/(1.f + expf(-o));
    } else {
        int b = bid - NB*T, c = tid;
        float th[T];
        #pragma unroll
        for (int t = 0; t < T; t++) {
            float s = 0.f;
            #pragma unroll 16
            for (int ss = 0; ss < SLOTS; ss++)
                s += g_partial[((size_t)(b*T + t)*SLOTS + ss)*C + c];
            th[t] = s * (1.0f/(float)HW);
        }
        float lg0 = 0.f, lg1 = 0.f, lg2 = 0.f;
        #pragma unroll 4
        for (int a = 0; a < AA; a++) {
            float g = 0.f;
            #pragma unroll
            for (int t = 0; t < T; t++) g += th[t] * gw1[t*AA + a];
            float inv = rsqrtf(gvar[a] + 1e-3f);
            g = (g - gmean[a]) * (ggam[a] * inv) + gbet[a];
            g = fmaxf(g, 0.f);
            lg0 += g * gw2[a*3 + 0];
            lg1 += g * gw2[a*3 + 1];
            lg2 += g * gw2[a*3 + 2];
        }
        float mx = fmaxf(lg0, fmaxf(lg1, lg2));
        float e0 = expf(lg0 - mx), e1 = expf(lg1 - mx), e2 = expf(lg2 - mx);
        float inv = 1.f/(e0 + e1 + e2);
        g_kern[(b*3 + 0)*C + c] = e0*inv;
        g_kern[(b*3 + 1)*C + c] = e1*inv;
        g_kern[(b*3 + 2)*C + c] = e2*inv;
    }
}

// ---------------- K3: fused gate + adaptive temporal conv, 2 p-streams ----
// y[b,c,t,p] = sum_k kern[b,c,k]*act[b,c,t-1+k]*x[b,c,t-1+k,p]
// Each block covers 8 spatial positions; each thread runs TWO independent
// p-streams (MLP=2). Reversed block order for L2 tail reuse; __stcs stores.
__global__ void k_agg(const float* __restrict__ x, float* __restrict__ y) {
    int tid = threadIdx.x;
    int b  = (NB - 1) - blockIdx.y;
    int pb = (gridDim.x - 1) - blockIdx.x;     // 0..97
    int c4 = tid & 63, pi = tid >> 6;
    int pA = pb*8 + pi;                        // stream A
    __shared__ float coef[T*3*C];              // 48 KB
    float k0 = g_kern[(b*3 + 0)*C + tid];
    float k1 = g_kern[(b*3 + 1)*C + tid];
    float k2 = g_kern[(b*3 + 2)*C + tid];
    coef[(0*3 + 0)*C + tid]  = 0.f;
    coef[(15*3 + 2)*C + tid] = 0.f;
    #pragma unroll
    for (int ts = 0; ts < T; ts++) {
        float a = g_act[(b*T + ts)*C + tid];
        #pragma unroll
        for (int k = 0; k < 3; k++) {
            int t = ts + 1 - k;
            if (t >= 0 && t < T) {
                float kk = (k == 0) ? k0 : ((k == 1) ? k1 : k2);
                coef[(t*3 + k)*C + tid] = kk * a;
            }
        }
    }
    __syncthreads();
    const float4* cs4 = (const float4*)coef;
    const int S4 = X4F;
    size_t baseA = (size_t)(b*T)*S4 + (size_t)pA*64 + c4;
    size_t baseB = baseA + 4*64;               // stream B: p = pA + 4
    const float4* xa = (const float4*)x + baseA;
    const float4* xb = (const float4*)x + baseB;
    float4*       ya = (float4*)y + baseA;
    float4*       yb = (float4*)y + baseB;
    float4 z = make_float4(0.f,0.f,0.f,0.f);
    float4 xmA = z, xcA = xa[0];
    float4 xmB = z, xcB = xb[0];
    #pragma unroll
    for (int t = 0; t < T; t++) {
        float4 xnA = (t < T-1) ? xa[(size_t)(t+1)*S4] : z;
        float4 xnB = (t < T-1) ? xb[(size_t)(t+1)*S4] : z;
        float4 c0 = cs4[(t*3 + 0)*64 + c4];
        float4 c1 = cs4[(t*3 + 1)*64 + c4];
        float4 c2 = cs4[(t*3 + 2)*64 + c4];
        float4 oA, oB;
        oA.x = c0.x*xmA.x + c1.x*xcA.x + c2.x*xnA.x;
        oA.y = c0.y*xmA.y + c1.y*xcA.y + c2.y*xnA.y;
        oA.z = c0.z*xmA.z + c1.z*xcA.z + c2.z*xnA.z;
        oA.w = c0.w*xmA.w + c1.w*xcA.w + c2.w*xnA.w;
        oB.x = c0.x*xmB.x + c1.x*xcB.x + c2.x*xnB.x;
        oB.y = c0.y*xmB.y + c1.y*xcB.y + c2.y*xnB.y;
        oB.z = c0.z*xmB.z + c1.z*xcB.z + c2.z*xnB.z;
        oB.w = c0.w*xmB.w + c1.w*xcB.w + c2.w*xnB.w;
        __stcs(ya + (size_t)t*S4, oA);
        __stcs(yb + (size_t)t*S4, oB);
        xmA = xcA; xcA = xnA;
        xmB = xcB; xcB = xnB;
    }
}

extern "C" void kernel_launch(void* const* d_in, const int* in_sizes, int n_in,
                              void* d_out, int out_size) {
    const float* x       = (const float*)d_in[0];
    const float* gw1     = (const float*)d_in[1];
    const float* ggamma  = (const float*)d_in[2];
    const float* gbeta   = (const float*)d_in[3];
    const float* gmean   = (const float*)d_in[4];
    const float* gvar    = (const float*)d_in[5];
    const float* gw2     = (const float*)d_in[6];
    const float* lw1     = (const float*)d_in[7];
    const float* lgamma  = (const float*)d_in[8];
    const float* lbeta   = (const float*)d_in[9];
    const float* lmean   = (const float*)d_in[10];
    const float* lvar    = (const float*)d_in[11];
    const float* lw2     = (const float*)d_in[12];
    float* y = (float*)d_out;

    k_partial<<<dim3(NB*T, NSPLIT), 256>>>((const float4*)x);
    k_branch <<<NB*T + NB, 256>>>(gw1, ggamma, gbeta, gmean, gvar, gw2,
                                  lw1, lgamma, lbeta, lmean, lvar, lw2);
    k_agg    <<<dim3(HW/8, NB), 256>>>(x, y);
}

// round 6
// speedup vs baseline: 1.3817x; 1.0460x over previous
#include <cuda_runtime.h>

#define NB 8
#define T 16
#define C 256
#define CM 64
#define AA 32
#define HW 784
#define HWC (HW*C)        /* 200704 */
#define X4F (HWC/4)       /* 50176 float4 per frame */
#define NSPLIT 16
#define ROWS_PER_SEG 49   /* 784/16 */
#define SLOTS (NSPLIT*4)  /* 64 partial slots per frame */

// Scratch (allocation-free rule: __device__ globals)
__device__ float g_partial[NB*T*SLOTS*C];   // 8 MB
__device__ float g_kern[NB*3*C];            // [b][k][c]
__device__ float g_act[NB*T*C];             // [b][t][c]

// ---------------- K1: spatial partial sums, float4, high-occupancy ----------
__global__ void k_partial(const float4* __restrict__ x4) {
    int n = blockIdx.x, s = blockIdx.y, tid = threadIdx.x;
    int c4 = tid & 63, pi = tid >> 6;
    const float4* xp = x4 + (size_t)n*X4F + (size_t)(s*ROWS_PER_SEG + pi)*64 + c4;
    float4 a0 = make_float4(0,0,0,0), a1 = a0, a2 = a0, a3 = a0;
    #pragma unroll
    for (int i = 0; i < 12; i += 4) {
        float4 v0 = xp[(size_t)(i+0)*256];
        float4 v1 = xp[(size_t)(i+1)*256];
        float4 v2 = xp[(size_t)(i+2)*256];
        float4 v3 = xp[(size_t)(i+3)*256];
        a0.x+=v0.x; a0.y+=v0.y; a0.z+=v0.z; a0.w+=v0.w;
        a1.x+=v1.x; a1.y+=v1.y; a1.z+=v1.z; a1.w+=v1.w;
        a2.x+=v2.x; a2.y+=v2.y; a2.z+=v2.z; a2.w+=v2.w;
        a3.x+=v3.x; a3.y+=v3.y; a3.z+=v3.z; a3.w+=v3.w;
    }
    if (pi == 0) {   // 49th row of the segment
        float4 v = xp[(size_t)12*256];
        a0.x+=v.x; a0.y+=v.y; a0.z+=v.z; a0.w+=v.w;
    }
    float4 r;
    r.x = (a0.x+a1.x)+(a2.x+a3.x);
    r.y = (a0.y+a1.y)+(a2.y+a3.y);
    r.z = (a0.z+a1.z)+(a2.z+a3.z);
    r.w = (a0.w+a1.w)+(a2.w+a3.w);
    ((float4*)g_partial)[((size_t)n*SLOTS + s*4 + pi)*64 + c4] = r;
}

// ---------------- K2: fused branch kernel ----------------
__global__ void k_branch(const float* __restrict__ gw1, const float* __restrict__ ggam,
                         const float* __restrict__ gbet, const float* __restrict__ gmean,
                         const float* __restrict__ gvar, const float* __restrict__ gw2,
                         const float* __restrict__ lw1, const float* __restrict__ lgam,
                         const float* __restrict__ lbet, const float* __restrict__ lmean,
                         const float* __restrict__ lvar, const float* __restrict__ lw2) {
    int bid = blockIdx.x, tid = threadIdx.x;
    if (bid < NB*T) {
        // local branch: conv(3,256->64)->bn/relu->conv(1,64->256)->sigmoid
        int b = bid / T, t = bid % T;
        __shared__ float th_s[3*C];
        __shared__ float red[256];
        __shared__ float l_s[CM];
        #pragma unroll
        for (int dt = 0; dt < 3; dt++) {
            int tt = t + dt - 1;
            float s = 0.f;
            if (tt >= 0 && tt < T) {
                #pragma unroll 16
                for (int ss = 0; ss < SLOTS; ss++)
                    s += g_partial[((size_t)(b*T + tt)*SLOTS + ss)*C + tid];
                s *= (1.0f/(float)HW);
            }
            th_s[dt*C + tid] = s;
        }
        __syncthreads();
        int m = tid & 63, part = tid >> 6;
        float acc = 0.f;
        #pragma unroll 8
        for (int i = 0; i < 192; i++) {
            int j = part*192 + i;                 // j = dt*256 + c
            acc += th_s[j] * lw1[j*CM + m];
        }
        red[tid] = acc;
        __syncthreads();
        if (tid < CM) {
            float v = red[tid] + red[tid+64] + red[tid+128] + red[tid+192];
            float inv = rsqrtf(lvar[tid] + 1e-3f);
            v = (v - lmean[tid]) * (lgam[tid] * inv) + lbet[tid];
            l_s[tid] = fmaxf(v, 0.f);
        }
        __syncthreads();
        float o = 0.f;
        #pragma unroll 8
        for (int mm = 0; mm < CM; mm++) o += l_s[mm] * lw2[mm*C + tid];
        g_act[(b*T + t)*C + tid] = 1.f/(1.f + expf(-o));
    } else {
        // global branch: Dense(16->32)->bn/relu->Dense(32->3)->softmax
        int b = bid - NB*T, c = tid;
        float th[T];
        #pragma unroll
        for (int t = 0; t < T; t++) {
            float s = 0.f;
            #pragma unroll 16
            for (int ss = 0; ss < SLOTS; ss++)
                s += g_partial[((size_t)(b*T + t)*SLOTS + ss)*C + c];
            th[t] = s * (1.0f/(float)HW);
        }
        float lg0 = 0.f, lg1 = 0.f, lg2 = 0.f;
        #pragma unroll 4
        for (int a = 0; a < AA; a++) {
            float g = 0.f;
            #pragma unroll
            for (int t = 0; t < T; t++) g += th[t] * gw1[t*AA + a];
            float inv = rsqrtf(gvar[a] + 1e-3f);
            g = (g - gmean[a]) * (ggam[a] * inv) + gbet[a];
            g = fmaxf(g, 0.f);
            lg0 += g * gw2[a*3 + 0];
            lg1 += g * gw2[a*3 + 1];
            lg2 += g * gw2[a*3 + 2];
        }
        float mx = fmaxf(lg0, fmaxf(lg1, lg2));
        float e0 = expf(lg0 - mx), e1 = expf(lg1 - mx), e2 = expf(lg2 - mx);
        float inv = 1.f/(e0 + e1 + e2);
        g_kern[(b*3 + 0)*C + c] = e0*inv;
        g_kern[(b*3 + 1)*C + c] = e1*inv;
        g_kern[(b*3 + 2)*C + c] = e2*inv;
    }
}

// ---------------- K3: gate + adaptive temporal conv, half-channel blocks ----
// y[b,c,t,p] = sum_k kern[b,c,k]*act[b,c,t-1+k]*x[b,c,t-1+k,p]
// Each block handles 128 channels x 8 spatial positions -> coef smem = 24 KB
// (doubles occupancy vs the 48 KB full-channel version). Single p-stream per
// thread, grid-reversed for L2 tail reuse, __stcs stores.
__global__ void __launch_bounds__(256) k_agg(const float* __restrict__ x,
                                             float* __restrict__ y) {
    int tid = threadIdx.x;
    int by = (gridDim.y - 1) - blockIdx.y;     // reversed: 0..15
    int b  = by >> 1;
    int ch = by & 1;                           // channel half
    int pb = (gridDim.x - 1) - blockIdx.x;     // reversed: 0..97
    int c4 = tid & 31, pi = tid >> 5;          // 32 float4 = 128 channels; 8 p's
    int p  = pb*8 + pi;
    __shared__ float coef[T*3*128];            // 24 KB: [t][k][128ch]

    // build coef for this block's 128 channels (2 ts-halves x 128 channels)
    {
        int cc = tid & 127;
        int h  = tid >> 7;                     // ts half: 0 -> ts 0..7, 1 -> ts 8..15
        int gc = ch*128 + cc;
        float k0 = g_kern[(b*3 + 0)*C + gc];
        float k1 = g_kern[(b*3 + 1)*C + gc];
        float k2 = g_kern[(b*3 + 2)*C + gc];
        if (h == 0) coef[(0*3 + 0)*128 + cc]  = 0.f;
        else        coef[(15*3 + 2)*128 + cc] = 0.f;
        #pragma unroll
        for (int i = 0; i < 8; i++) {
            int ts = h*8 + i;
            float a = g_act[(b*T + ts)*C + gc];
            #pragma unroll
            for (int k = 0; k < 3; k++) {
                int t = ts + 1 - k;            // output time sourcing ts with tap k
                if (t >= 0 && t < T) {
                    float kk = (k == 0) ? k0 : ((k == 1) ? k1 : k2);
                    coef[(t*3 + k)*128 + cc] = kk * a;
                }
            }
        }
    }
    __syncthreads();

    const float4* cs4 = (const float4*)coef;
    const int S4 = X4F;
    size_t base4 = (size_t)(b*T)*S4 + (size_t)p*64 + (size_t)ch*32 + c4;
    const float4* xp = (const float4*)x + base4;
    float4*       yp = (float4*)y + base4;
    float4 z = make_float4(0.f,0.f,0.f,0.f);
    float4 xm = z;
    float4 xc = xp[0];
    #pragma unroll
    for (int t = 0; t < T; t++) {
        float4 xn = (t < T-1) ? xp[(size_t)(t+1)*S4] : z;
        float4 c0 = cs4[(t*3 + 0)*32 + c4];
        float4 c1 = cs4[(t*3 + 1)*32 + c4];
        float4 c2 = cs4[(t*3 + 2)*32 + c4];
        float4 o;
        o.x = c0.x*xm.x + c1.x*xc.x + c2.x*xn.x;
        o.y = c0.y*xm.y + c1.y*xc.y + c2.y*xn.y;
        o.z = c0.z*xm.z + c1.z*xc.z + c2.z*xn.z;
        o.w = c0.w*xm.w + c1.w*xc.w + c2.w*xn.w;
        __stcs(yp + (size_t)t*S4, o);
        xm = xc; xc = xn;
    }
}

extern "C" void kernel_launch(void* const* d_in, const int* in_sizes, int n_in,
                              void* d_out, int out_size) {
    const float* x       = (const float*)d_in[0];
    const float* gw1     = (const float*)d_in[1];
    const float* ggamma  = (const float*)d_in[2];
    const float* gbeta   = (const float*)d_in[3];
    const float* gmean   = (const float*)d_in[4];
    const float* gvar    = (const float*)d_in[5];
    const float* gw2     = (const float*)d_in[6];
    const float* lw1     = (const float*)d_in[7];
    const float* lgamma  = (const float*)d_in[8];
    const float* lbeta   = (const float*)d_in[9];
    const float* lmean   = (const float*)d_in[10];
    const float* lvar    = (const float*)d_in[11];
    const float* lw2     = (const float*)d_in[12];
    float* y = (float*)d_out;

    k_partial<<<dim3(NB*T, NSPLIT), 256>>>((const float4*)x);
    k_branch <<<NB*T + NB, 256>>>(gw1, ggamma, gbeta, gmean, gvar, gw2,
                                  lw1, lgamma, lbeta, lmean, lvar, lw2);
    k_agg    <<<dim3(HW/8, NB*2), 256>>>(x, y);
}